// round 6
// baseline (speedup 1.0000x reference)
#include <cuda_runtime.h>
#include <math.h>
#include <stdint.h>

#define Bsz   64
#define Tlen  512
#define HID   512
#define G4    2048      // 4*HID gate rows
#define CTX   792
#define IND   1048
#define BCL   8
#define VOC   260
#define PBL   (Tlen + BCL)   // 520
#define PJ    (BCL * VOC)    // 2080
#define GRIDR 128            // persistent recurrent blocks (<=148 SMs, 1 CTA/SM)
#define UPB   4              // hidden units per block (128*4 = 512)

// ---------------- device scratch (static globals: no allocation APIs) ------
__device__ float g_ctx[Bsz * CTX];                 // assembled context
__device__ int   g_pb[Bsz * PBL];                  // padded byte stream
__device__ float g_gctx0[G4 * Bsz];                // W_ih0[:, :792]@ctx + b_ih0 + b_hh0, [g][b]
__device__ float g_P[(size_t)G4 * PJ];             // byte-projection table [g][j][v]  (~17MB)
__device__ float g_h[2][Bsz * HID];                // double-buffered hidden state
__device__ float g_h1[(size_t)Tlen * Bsz * HID];   // layer-0 outputs [t][b][j] (64MB)
__device__ float g_h2[(size_t)Tlen * Bsz * HID];   // layer-1 outputs [t][b][j] (64MB)
__device__ unsigned g_cnt = 0;
__device__ unsigned g_gen = 0;

// ---------------- helpers --------------------------------------------------
__device__ __forceinline__ void fma2(unsigned long long& acc,
                                     unsigned long long a, unsigned long long b) {
    asm("fma.rn.f32x2 %0, %1, %2, %0;" : "+l"(acc) : "l"(a), "l"(b));
}
__device__ __forceinline__ float usum(unsigned long long v) {
    float lo = __uint_as_float((unsigned)(v & 0xffffffffull));
    float hi = __uint_as_float((unsigned)(v >> 32));
    return lo + hi;
}
__device__ __forceinline__ float sigf(float x) { return 1.f / (1.f + expf(-x)); }

// Software grid barrier. Safe because grid==GRIDR blocks, 1 CTA/SM, all co-resident.
__device__ __forceinline__ void gridbar() {
    __syncthreads();
    if (threadIdx.x == 0) {
        unsigned gen;
        asm volatile("ld.acquire.gpu.global.u32 %0, [%1];" : "=r"(gen) : "l"(&g_gen) : "memory");
        __threadfence();                         // release my writes before arriving
        unsigned my = atomicAdd(&g_cnt, 1u);
        if (my == (unsigned)(GRIDR - 1)) {
            atomicExch(&g_cnt, 0u);
            __threadfence();
            atomicAdd(&g_gen, 1u);               // release everyone
        } else {
            unsigned cur;
            do {
                __nanosleep(64);
                asm volatile("ld.acquire.gpu.global.u32 %0, [%1];" : "=r"(cur) : "l"(&g_gen) : "memory");
            } while (cur == gen);
        }
    }
    __syncthreads();
}

// ---------------- K0: context assembly + padded byte stream ----------------
__global__ void k_prep(const float* __restrict__ ecc, const int* __restrict__ cat,
                       const float* __restrict__ num, const int* __restrict__ pay,
                       const float* __restrict__ e0, const float* __restrict__ e1,
                       const float* __restrict__ e2) {
    int b = blockIdx.x;
    int c0 = cat[b * 3 + 0], c1 = cat[b * 3 + 1], c2 = cat[b * 3 + 2];
    for (int i = threadIdx.x; i < CTX; i += blockDim.x) {
        float v;
        if (i < 512)      v = ecc[b * 512 + i];
        else if (i < 562) v = e0[c0 * 50 + (i - 512)];
        else if (i < 626) v = e1[c1 * 64 + (i - 562)];
        else if (i < 776) v = e2[c2 * 150 + (i - 626)];
        else              v = num[b * 16 + (i - 776)];
        g_ctx[b * CTX + i] = v;
    }
    for (int p = threadIdx.x; p < PBL; p += blockDim.x) {
        int v = (p < BCL - 1) ? 256 : (p == BCL - 1 ? 257 : pay[b * Tlen + p - BCL]);
        g_pb[b * PBL + p] = v;
    }
}

// ---------------- K1: context gate projection (constant over t) ------------
__global__ void k_gctx(const float* __restrict__ Wih0, const float* __restrict__ bih0,
                       const float* __restrict__ bhh0) {
    int g = blockIdx.x;            // 2048 blocks
    int b = threadIdx.x;           // 64 threads
    const float* w = Wih0 + (size_t)g * IND;
    const float* c = g_ctx + b * CTX;
    float acc = bih0[g] + bhh0[g];
    for (int k = 0; k < CTX; k++) acc += w[k] * c[k];
    g_gctx0[g * Bsz + b] = acc;
}

// ---------------- K2: byte-projection table P[g][j][v] ---------------------
__global__ void k_table(const float* __restrict__ Wih0, const float* __restrict__ be) {
    __shared__ float ws[BCL * 32];       // window slice of W row (256 floats)
    __shared__ float es[VOC * 33];       // byte_emb, padded stride 33 (bank-safe)
    int g = blockIdx.x, tid = threadIdx.x;
    if (tid < 256) ws[tid] = Wih0[(size_t)g * IND + CTX + tid];
    for (int i = tid; i < VOC * 32; i += blockDim.x) {
        int v = i >> 5, k = i & 31;
        es[v * 33 + k] = be[i];
    }
    __syncthreads();
    for (int idx = tid; idx < PJ; idx += blockDim.x) {
        int j = idx / VOC, v = idx - j * VOC;
        const float* w = ws + j * 32;
        const float* e = es + v * 33;
        float acc = 0.f;
#pragma unroll
        for (int k = 0; k < 32; k++) acc += w[k] * e[k];
        g_P[(size_t)g * PJ + idx] = acc;
    }
}

// ---------------- K3: layer-0 recurrence (persistent) ----------------------
// block bid owns hidden units j0..j0+3; local row lr = u*4 + gate; global row = 512*gate + j0 + u
__global__ void __launch_bounds__(256, 1) k_l0(const float* __restrict__ Whh0) {
    extern __shared__ float dsm[];
    float* Wsh = dsm;                    // [16][512]
    float* Psh = dsm + 16 * HID;         // [16][2080]
    __shared__ float ex[Bsz * 16];
    __shared__ float csh[UPB * Bsz];

    int tid = threadIdx.x;
    int j0  = blockIdx.x * UPB;

    for (int i = tid; i < 16 * HID; i += 256) {
        int lr = i >> 9, k = i & 511;
        int grow = ((lr & 3) << 9) + j0 + (lr >> 2);
        Wsh[i] = Whh0[(size_t)grow * HID + k];
    }
    for (int i = tid; i < 16 * PJ; i += 256) {
        int lr = i / PJ, r = i - lr * PJ;
        int grow = ((lr & 3) << 9) + j0 + (lr >> 2);
        Psh[i] = g_P[(size_t)grow * PJ + r];
    }
    for (int i = tid; i < UPB * Bsz; i += 256) csh[i] = 0.f;

    int b = tid >> 2, q = tid & 3;       // GEMM phase: thread = (batch b, gate q)
    float gc[UPB];
    const float* wp[UPB];
    const float* pp[UPB];
#pragma unroll
    for (int u = 0; u < UPB; u++) {
        int grow = (q << 9) + j0 + u;
        gc[u] = g_gctx0[grow * Bsz + b];
        wp[u] = Wsh + (u * 4 + q) * HID;
        pp[u] = Psh + (u * 4 + q) * PJ;
    }
    const int* pbb = g_pb + b * PBL;
    __syncthreads();

    for (int t = 0; t < Tlen; t++) {
        float acc[UPB];
        if (t == 0) {
#pragma unroll
            for (int u = 0; u < UPB; u++) acc[u] = gc[u];
        } else {
            unsigned long long a0[UPB] = {0,0,0,0}, a1[UPB] = {0,0,0,0};
            const float* hrow = g_h[t & 1] + b * HID;
#pragma unroll 4
            for (int k = 0; k < HID; k += 4) {
                ulonglong2 h4 = __ldcg(reinterpret_cast<const ulonglong2*>(hrow + k));
#pragma unroll
                for (int u = 0; u < UPB; u++) {
                    ulonglong2 w4 = *reinterpret_cast<const ulonglong2*>(wp[u] + k);
                    fma2(a0[u], h4.x, w4.x);
                    fma2(a1[u], h4.y, w4.y);
                }
            }
#pragma unroll
            for (int u = 0; u < UPB; u++) acc[u] = gc[u] + usum(a0[u]) + usum(a1[u]);
        }
        // sliding-window byte table adds (input transform, window part)
#pragma unroll
        for (int j = 0; j < BCL; j++) {
            int v = pbb[t + j];
#pragma unroll
            for (int u = 0; u < UPB; u++) acc[u] += pp[u][j * VOC + v];
        }
#pragma unroll
        for (int u = 0; u < UPB; u++) ex[b * 16 + u * 4 + q] = acc[u];
        __syncthreads();
        {   // combine phase: thread = (batch b, unit q)
            float gi = ex[b * 16 + q * 4 + 0];
            float gf = ex[b * 16 + q * 4 + 1];
            float gg = ex[b * 16 + q * 4 + 2];
            float go = ex[b * 16 + q * 4 + 3];
            float c  = csh[q * Bsz + b];
            c = sigf(gf) * c + sigf(gi) * tanhf(gg);
            float h = sigf(go) * tanhf(c);
            csh[q * Bsz + b] = c;
            int j = j0 + q;
            g_h[(t + 1) & 1][b * HID + j] = h;
            g_h1[((size_t)t * Bsz + b) * HID + j] = h;
        }
        gridbar();
    }
}

// ---------------- K4: layer-1 recurrence (fused input GEMM) ----------------
__global__ void __launch_bounds__(256, 1) k_l1(const float* __restrict__ Whh1,
                                               const float* __restrict__ Wih1,
                                               const float* __restrict__ bih1,
                                               const float* __restrict__ bhh1) {
    extern __shared__ float dsm[];
    float* Wh = dsm;                 // [16][512] recurrent
    float* Wi = dsm + 16 * HID;      // [16][512] input
    __shared__ float ex[Bsz * 16];
    __shared__ float csh[UPB * Bsz];

    int tid = threadIdx.x;
    int j0  = blockIdx.x * UPB;
    for (int i = tid; i < 16 * HID; i += 256) {
        int lr = i >> 9, k = i & 511;
        int grow = ((lr & 3) << 9) + j0 + (lr >> 2);
        Wh[i] = Whh1[(size_t)grow * HID + k];
        Wi[i] = Wih1[(size_t)grow * HID + k];
    }
    for (int i = tid; i < UPB * Bsz; i += 256) csh[i] = 0.f;

    int b = tid >> 2, q = tid & 3;
    float bias[UPB];
    const float* whp[UPB];
    const float* wip[UPB];
#pragma unroll
    for (int u = 0; u < UPB; u++) {
        int grow = (q << 9) + j0 + u;
        bias[u] = bih1[grow] + bhh1[grow];
        whp[u] = Wh + (u * 4 + q) * HID;
        wip[u] = Wi + (u * 4 + q) * HID;
    }
    __syncthreads();

    for (int t = 0; t < Tlen; t++) {
        unsigned long long a0[UPB] = {0,0,0,0}, a1[UPB] = {0,0,0,0};
        // input transform: W_ih1 @ h1[t]  (layer-0 output, written by previous kernel)
        const float* xrow = g_h1 + ((size_t)t * Bsz + b) * HID;
#pragma unroll 4
        for (int k = 0; k < HID; k += 4) {
            ulonglong2 h4 = *reinterpret_cast<const ulonglong2*>(xrow + k);
#pragma unroll
            for (int u = 0; u < UPB; u++) {
                ulonglong2 w4 = *reinterpret_cast<const ulonglong2*>(wip[u] + k);
                fma2(a0[u], h4.x, w4.x);
                fma2(a1[u], h4.y, w4.y);
            }
        }
        if (t > 0) {
            const float* hrow = g_h[t & 1] + b * HID;
#pragma unroll 4
            for (int k = 0; k < HID; k += 4) {
                ulonglong2 h4 = __ldcg(reinterpret_cast<const ulonglong2*>(hrow + k));
#pragma unroll
                for (int u = 0; u < UPB; u++) {
                    ulonglong2 w4 = *reinterpret_cast<const ulonglong2*>(whp[u] + k);
                    fma2(a0[u], h4.x, w4.x);
                    fma2(a1[u], h4.y, w4.y);
                }
            }
        }
        float acc[UPB];
#pragma unroll
        for (int u = 0; u < UPB; u++) acc[u] = bias[u] + usum(a0[u]) + usum(a1[u]);
#pragma unroll
        for (int u = 0; u < UPB; u++) ex[b * 16 + u * 4 + q] = acc[u];
        __syncthreads();
        {
            float gi = ex[b * 16 + q * 4 + 0];
            float gf = ex[b * 16 + q * 4 + 1];
            float gg = ex[b * 16 + q * 4 + 2];
            float go = ex[b * 16 + q * 4 + 3];
            float c  = csh[q * Bsz + b];
            c = sigf(gf) * c + sigf(gi) * tanhf(gg);
            float h = sigf(go) * tanhf(c);
            csh[q * Bsz + b] = c;
            int j = j0 + q;
            g_h[(t + 1) & 1][b * HID + j] = h;
            g_h2[((size_t)t * Bsz + b) * HID + j] = h;
        }
        gridbar();
    }
}

// ---------------- K5: output head ------------------------------------------
__global__ void __launch_bounds__(256, 1) k_out(const float* __restrict__ Wout,
                                                const float* __restrict__ bout,
                                                float* __restrict__ out) {
    extern __shared__ float dsm[];           // Wsh[64][512]
    int vc = blockIdx.x;                     // 0..3 (chunks of 64 vocab rows)
    int t  = blockIdx.y;                     // 0..511
    for (int i = threadIdx.x; i < 64 * HID; i += 256)
        dsm[i] = Wout[(size_t)(vc * 64) * HID + i];
    __syncthreads();

    int tid = threadIdx.x;
    int b = tid >> 2, vg = tid & 3;          // 64 batches x 4 groups of 16 vocab
    unsigned long long acc[16];
#pragma unroll
    for (int i = 0; i < 16; i++) acc[i] = 0ull;
    const float* hrow  = g_h2 + ((size_t)t * Bsz + b) * HID;
    const float* wbase = dsm + (vg * 16) * HID;
#pragma unroll 2
    for (int k = 0; k < HID; k += 4) {
        ulonglong2 h4 = *reinterpret_cast<const ulonglong2*>(hrow + k);
#pragma unroll
        for (int i = 0; i < 16; i++) {
            ulonglong2 w4 = *reinterpret_cast<const ulonglong2*>(wbase + i * HID + k);
            fma2(acc[i], h4.x, w4.x);
            fma2(acc[i], h4.y, w4.y);
        }
    }
#pragma unroll
    for (int i = 0; i < 16; i++) {
        int v = vc * 64 + vg * 16 + i;
        out[((size_t)b * Tlen + t) * 256 + v] = usum(acc[i]) + bout[v];
    }
}

// ---------------- launch ----------------------------------------------------
extern "C" void kernel_launch(void* const* d_in, const int* in_sizes, int n_in,
                              void* d_out, int out_size) {
    (void)in_sizes; (void)n_in; (void)out_size;
    const float* ecc  = (const float*)d_in[0];
    const int*   cat  = (const int*)  d_in[1];
    const float* num  = (const float*)d_in[2];
    const int*   pay  = (const int*)  d_in[3];
    const float* e0   = (const float*)d_in[4];
    const float* e1   = (const float*)d_in[5];
    const float* e2   = (const float*)d_in[6];
    const float* be   = (const float*)d_in[7];
    const float* Wih0 = (const float*)d_in[8];
    const float* Whh0 = (const float*)d_in[9];
    const float* bih0 = (const float*)d_in[10];
    const float* bhh0 = (const float*)d_in[11];
    const float* Wih1 = (const float*)d_in[12];
    const float* Whh1 = (const float*)d_in[13];
    const float* bih1 = (const float*)d_in[14];
    const float* bhh1 = (const float*)d_in[15];
    const float* Wout = (const float*)d_in[16];
    const float* bout = (const float*)d_in[17];
    float* out = (float*)d_out;

    const int SM_L0  = (16 * HID + 16 * PJ) * 4;   // 165,888 B
    const int SM_L1  = (2 * 16 * HID) * 4;         //  65,536 B
    const int SM_OUT = (64 * HID) * 4;             // 131,072 B
    cudaFuncSetAttribute(k_l0,  cudaFuncAttributeMaxDynamicSharedMemorySize, SM_L0);
    cudaFuncSetAttribute(k_l1,  cudaFuncAttributeMaxDynamicSharedMemorySize, SM_L1);
    cudaFuncSetAttribute(k_out, cudaFuncAttributeMaxDynamicSharedMemorySize, SM_OUT);

    k_prep <<<Bsz, 128>>>(ecc, cat, num, pay, e0, e1, e2);
    k_gctx <<<G4, 64>>>(Wih0, bih0, bhh0);
    k_table<<<G4, 256>>>(Wih0, be);
    k_l0   <<<GRIDR, 256, SM_L0>>>(Whh0);
    k_l1   <<<GRIDR, 256, SM_L1>>>(Whh1, Wih1, bih1, bhh1);
    dim3 go(4, Tlen);
    k_out  <<<go, 256, SM_OUT>>>(Wout, bout, out);
}

// round 7
// speedup vs baseline: 2.5879x; 2.5879x over previous
#include <cuda_runtime.h>
#include <math.h>
#include <stdint.h>

#define Bsz   64
#define Tlen  512
#define HID   512
#define G4    2048
#define CTX   792
#define IND   1048
#define BCL   8
#define VOC   260
#define PBL   (Tlen + BCL)   // 520
#define PJ    (BCL * VOC)    // 2080
#define WP    516            // padded W row stride (516 mod 32 == 4 -> conflict-free)
#define PP    2084           // padded P row stride
#define GRIDR 128
#define UPB   4

// ---------------- device scratch ------------------------------------------
__device__ float g_ctx[Bsz * CTX];
__device__ int   g_pb[Bsz * PBL];
__device__ float g_gctx0[G4 * Bsz];
__device__ float g_P[(size_t)G4 * PJ];             // ~17MB, L2-resident
__device__ float g_h[2][Bsz * HID];                // double-buffered h exchange
__device__ float g_h1[(size_t)Tlen * Bsz * HID];   // layer-0 outputs
__device__ float g_h2[(size_t)Tlen * Bsz * HID];   // layer-1 outputs
__device__ unsigned g_flag[GRIDR];                 // barrier flags (monotonic)

// ---------------- helpers --------------------------------------------------
__device__ __forceinline__ void fma2(unsigned long long& acc,
                                     unsigned long long a, unsigned long long b) {
    asm("fma.rn.f32x2 %0, %1, %2, %0;" : "+l"(acc) : "l"(a), "l"(b));
}
__device__ __forceinline__ float usum(unsigned long long v) {
    float lo = __uint_as_float((unsigned)(v & 0xffffffffull));
    float hi = __uint_as_float((unsigned)(v >> 32));
    return lo + hi;
}
__device__ __forceinline__ float sigf(float x) {
    return __fdividef(1.f, 1.f + __expf(-x));
}
__device__ __forceinline__ float tanh_fast(float x) {
    return __fmaf_rn(2.f, sigf(2.f * x), -1.f);
}

// Barrier: arrival = one release-store to own slot.
__device__ __forceinline__ void bar_arrive(int bid, unsigned val) {
    asm volatile("st.release.gpu.global.u32 [%0], %1;"
                 :: "l"(g_flag + bid), "r"(val) : "memory");
}
// Wait: warp 0 only. Lane L polls slots 4L..4L+3 via one v4 load per round.
__device__ __forceinline__ void bar_wait(unsigned target) {
    const unsigned* p = g_flag + ((threadIdx.x & 31) << 2);
    for (;;) {
        unsigned x, y, z, w;
        asm volatile("ld.relaxed.gpu.global.v4.u32 {%0,%1,%2,%3}, [%4];"
                     : "=r"(x), "=r"(y), "=r"(z), "=r"(w) : "l"(p));
        bool ok = (x >= target) && (y >= target) && (z >= target) && (w >= target);
        if (__all_sync(0xffffffffu, ok)) break;
    }
    asm volatile("fence.acq_rel.gpu;" ::: "memory");
}
__device__ __forceinline__ unsigned flag_base(int bid) {
    unsigned v;
    asm volatile("ld.relaxed.gpu.global.u32 %0, [%1];" : "=r"(v) : "l"(g_flag + bid));
    return v;
}

// ---------------- K0: context assembly + padded byte stream ----------------
__global__ void k_prep(const float* __restrict__ ecc, const int* __restrict__ cat,
                       const float* __restrict__ num, const int* __restrict__ pay,
                       const float* __restrict__ e0, const float* __restrict__ e1,
                       const float* __restrict__ e2) {
    int b = blockIdx.x;
    int c0 = cat[b * 3 + 0], c1 = cat[b * 3 + 1], c2 = cat[b * 3 + 2];
    for (int i = threadIdx.x; i < CTX; i += blockDim.x) {
        float v;
        if (i < 512)      v = ecc[b * 512 + i];
        else if (i < 562) v = e0[c0 * 50 + (i - 512)];
        else if (i < 626) v = e1[c1 * 64 + (i - 562)];
        else if (i < 776) v = e2[c2 * 150 + (i - 626)];
        else              v = num[b * 16 + (i - 776)];
        g_ctx[b * CTX + i] = v;
    }
    for (int p = threadIdx.x; p < PBL; p += blockDim.x) {
        int v = (p < BCL - 1) ? 256 : (p == BCL - 1 ? 257 : pay[b * Tlen + p - BCL]);
        g_pb[b * PBL + p] = v;
    }
}

// ---------------- K1: context gate projection ------------------------------
__global__ void k_gctx(const float* __restrict__ Wih0, const float* __restrict__ bih0,
                       const float* __restrict__ bhh0) {
    int g = blockIdx.x;
    int b = threadIdx.x;
    const float* w = Wih0 + (size_t)g * IND;
    const float* c = g_ctx + b * CTX;
    float acc = bih0[g] + bhh0[g];
    for (int k = 0; k < CTX; k++) acc += w[k] * c[k];
    g_gctx0[g * Bsz + b] = acc;
}

// ---------------- K2: byte-projection table P[g][j][v] ---------------------
__global__ void k_table(const float* __restrict__ Wih0, const float* __restrict__ be) {
    __shared__ float ws[BCL * 32];
    __shared__ float es[VOC * 33];
    int g = blockIdx.x, tid = threadIdx.x;
    if (tid < 256) ws[tid] = Wih0[(size_t)g * IND + CTX + tid];
    for (int i = tid; i < VOC * 32; i += blockDim.x) {
        int v = i >> 5, k = i & 31;
        es[v * 33 + k] = be[i];
    }
    __syncthreads();
    for (int idx = tid; idx < PJ; idx += blockDim.x) {
        int j = idx / VOC, v = idx - j * VOC;
        const float* w = ws + j * 32;
        const float* e = es + v * 33;
        float acc = 0.f;
#pragma unroll
        for (int k = 0; k < 32; k++) acc += w[k] * e[k];
        g_P[(size_t)g * PJ + idx] = acc;
    }
}

// ---------------- K3: layer-0 recurrence (persistent) ----------------------
__global__ void __launch_bounds__(256) k_l0(const float* __restrict__ Whh0) {
    extern __shared__ float dsm[];
    float* Wsh = dsm;                // [16][WP]
    float* Psh = dsm + 16 * WP;      // [16][PP]
    __shared__ float ex[Bsz * 16];

    int tid = threadIdx.x, bid = blockIdx.x;
    int j0 = bid * UPB;
    unsigned base = flag_base(bid);

    for (int i = tid; i < 16 * HID; i += 256) {
        int lr = i >> 9, k = i & 511;
        int grow = ((lr & 3) << 9) + j0 + (lr >> 2);
        Wsh[lr * WP + k] = Whh0[(size_t)grow * HID + k];
    }
    for (int i = tid; i < 16 * PJ; i += 256) {
        int lr = i / PJ, r = i - lr * PJ;
        int grow = ((lr & 3) << 9) + j0 + (lr >> 2);
        Psh[lr * PP + r] = g_P[(size_t)grow * PJ + r];
    }

    int b = tid >> 2, q = tid & 3;
    float gc[UPB];
    const float* wp_[UPB];
    const float* pp_[UPB];
#pragma unroll
    for (int u = 0; u < UPB; u++) {
        int grow = (q << 9) + j0 + u;
        gc[u] = g_gctx0[grow * Bsz + b];
        wp_[u] = Wsh + (u * 4 + q) * WP;
        pp_[u] = Psh + (u * 4 + q) * PP;
    }
    const int* pbb = g_pb + b * PBL;
    int vwin[BCL];
#pragma unroll
    for (int j = 0; j < BCL; j++) vwin[j] = pbb[j];
    float creg = 0.f;
    __syncthreads();

    for (int t = 0; t < Tlen; t++) {
        // phase A: window gather (no dependence on barrier)
        float acc[UPB];
#pragma unroll
        for (int u = 0; u < UPB; u++) acc[u] = gc[u];
#pragma unroll
        for (int j = 0; j < BCL; j++) {
            int off = j * VOC + vwin[j];
#pragma unroll
            for (int u = 0; u < UPB; u++) acc[u] += pp_[u][off];
        }
        // phase B: wait for h(t), then recurrent GEMM with 8-deep prefetch
        if (t > 0) {
            if (tid < 32) bar_wait(base + t);
            __syncthreads();
            const ulonglong2* hp = (const ulonglong2*)(g_h[t & 1] + b * HID);
            unsigned long long a0[UPB] = {0,0,0,0}, a1[UPB] = {0,0,0,0};
            ulonglong2 buf[8];
#pragma unroll
            for (int i = 0; i < 8; i++) buf[i] = __ldcg(hp + i);
            for (int kc = 0; kc < 128; kc += 8) {
#pragma unroll
                for (int i = 0; i < 8; i++) {
                    ulonglong2 h4 = buf[i];
                    int nxt = kc + 8 + i;
                    if (nxt < 128) buf[i] = __ldcg(hp + nxt);
                    int k = (kc + i) * 4;
#pragma unroll
                    for (int u = 0; u < UPB; u++) {
                        ulonglong2 w4 = *(const ulonglong2*)(wp_[u] + k);
                        fma2(a0[u], h4.x, w4.x);
                        fma2(a1[u], h4.y, w4.y);
                    }
                }
            }
#pragma unroll
            for (int u = 0; u < UPB; u++) acc[u] += usum(a0[u]) + usum(a1[u]);
        }
        // exchange + combine (c lives in a register of thread (b, unit q))
#pragma unroll
        for (int u = 0; u < UPB; u++) ex[b * 16 + u * 4 + q] = acc[u];
        __syncthreads();
        {
            float4 g = *(const float4*)(ex + b * 16 + q * 4);
            float c = sigf(g.y) * creg + sigf(g.x) * tanh_fast(g.z);
            float h = sigf(g.w) * tanh_fast(c);
            creg = c;
            int j = j0 + q;
            g_h[(t + 1) & 1][b * HID + j] = h;
            g_h1[((size_t)t * Bsz + b) * HID + j] = h;
        }
        __syncthreads();
        if (tid == 0) bar_arrive(bid, base + t + 1);
        // slide window for next step
#pragma unroll
        for (int j2 = 0; j2 < BCL - 1; j2++) vwin[j2] = vwin[j2 + 1];
        vwin[BCL - 1] = pbb[t + BCL];
    }
}

// ---------------- K4: layer-1 recurrence (x-GEMM overlaps barrier) ---------
__global__ void __launch_bounds__(256) k_l1(const float* __restrict__ Whh1,
                                            const float* __restrict__ Wih1,
                                            const float* __restrict__ bih1,
                                            const float* __restrict__ bhh1) {
    extern __shared__ float dsm[];
    float* Wh = dsm;                 // [16][WP]
    float* Wi = dsm + 16 * WP;       // [16][WP]
    __shared__ float ex[Bsz * 16];

    int tid = threadIdx.x, bid = blockIdx.x;
    int j0 = bid * UPB;
    unsigned base = flag_base(bid);

    for (int i = tid; i < 16 * HID; i += 256) {
        int lr = i >> 9, k = i & 511;
        int grow = ((lr & 3) << 9) + j0 + (lr >> 2);
        Wh[lr * WP + k] = Whh1[(size_t)grow * HID + k];
        Wi[lr * WP + k] = Wih1[(size_t)grow * HID + k];
    }

    int b = tid >> 2, q = tid & 3;
    float bias[UPB];
    const float* whp[UPB];
    const float* wip[UPB];
#pragma unroll
    for (int u = 0; u < UPB; u++) {
        int grow = (q << 9) + j0 + u;
        bias[u] = bih1[grow] + bhh1[grow];
        whp[u] = Wh + (u * 4 + q) * WP;
        wip[u] = Wi + (u * 4 + q) * WP;
    }
    float creg = 0.f;
    __syncthreads();

    for (int t = 0; t < Tlen; t++) {
        unsigned long long a0[UPB] = {0,0,0,0}, a1[UPB] = {0,0,0,0};
        // phase A: input transform (independent of barrier -> hides sync)
        {
            const ulonglong2* xp =
                (const ulonglong2*)(g_h1 + ((size_t)t * Bsz + b) * HID);
            ulonglong2 buf[8];
#pragma unroll
            for (int i = 0; i < 8; i++) buf[i] = __ldcg(xp + i);
            for (int kc = 0; kc < 128; kc += 8) {
#pragma unroll
                for (int i = 0; i < 8; i++) {
                    ulonglong2 h4 = buf[i];
                    int nxt = kc + 8 + i;
                    if (nxt < 128) buf[i] = __ldcg(xp + nxt);
                    int k = (kc + i) * 4;
#pragma unroll
                    for (int u = 0; u < UPB; u++) {
                        ulonglong2 w4 = *(const ulonglong2*)(wip[u] + k);
                        fma2(a0[u], h4.x, w4.x);
                        fma2(a1[u], h4.y, w4.y);
                    }
                }
            }
        }
        // phase B: wait for h2(t), recurrent GEMM
        if (t > 0) {
            if (tid < 32) bar_wait(base + t);
            __syncthreads();
            const ulonglong2* hp = (const ulonglong2*)(g_h[t & 1] + b * HID);
            ulonglong2 buf[8];
#pragma unroll
            for (int i = 0; i < 8; i++) buf[i] = __ldcg(hp + i);
            for (int kc = 0; kc < 128; kc += 8) {
#pragma unroll
                for (int i = 0; i < 8; i++) {
                    ulonglong2 h4 = buf[i];
                    int nxt = kc + 8 + i;
                    if (nxt < 128) buf[i] = __ldcg(hp + nxt);
                    int k = (kc + i) * 4;
#pragma unroll
                    for (int u = 0; u < UPB; u++) {
                        ulonglong2 w4 = *(const ulonglong2*)(whp[u] + k);
                        fma2(a0[u], h4.x, w4.x);
                        fma2(a1[u], h4.y, w4.y);
                    }
                }
            }
        }
        float acc[UPB];
#pragma unroll
        for (int u = 0; u < UPB; u++) acc[u] = bias[u] + usum(a0[u]) + usum(a1[u]);
#pragma unroll
        for (int u = 0; u < UPB; u++) ex[b * 16 + u * 4 + q] = acc[u];
        __syncthreads();
        {
            float4 g = *(const float4*)(ex + b * 16 + q * 4);
            float c = sigf(g.y) * creg + sigf(g.x) * tanh_fast(g.z);
            float h = sigf(g.w) * tanh_fast(c);
            creg = c;
            int j = j0 + q;
            g_h[(t + 1) & 1][b * HID + j] = h;
            g_h2[((size_t)t * Bsz + b) * HID + j] = h;
        }
        __syncthreads();
        if (tid == 0) bar_arrive(bid, base + t + 1);
    }
}

// ---------------- K5: output head (16 timesteps per weight-tile load) ------
#define OW 516   // padded smem row stride for Wout
__global__ void __launch_bounds__(256) k_out(const float* __restrict__ Wout,
                                             const float* __restrict__ bout,
                                             float* __restrict__ out) {
    extern __shared__ float dsm[];           // [64][OW]
    int vc = blockIdx.x;                     // 0..3  (64 vocab rows each)
    int ts = blockIdx.y;                     // 0..31 (16 timesteps each)
    int tid = threadIdx.x;
    for (int i = tid; i < 64 * HID; i += 256) {
        int r = i >> 9, k = i & 511;
        dsm[r * OW + k] = Wout[(size_t)(vc * 64 + r) * HID + k];
    }
    __syncthreads();

    int b = tid >> 2, vg = tid & 3;          // rows vg, vg+4, ..., vg+60 (interleaved)
    float bo[16];
#pragma unroll
    for (int i = 0; i < 16; i++) bo[i] = bout[vc * 64 + vg + i * 4];

    for (int tt = 0; tt < 16; tt++) {
        int t = ts * 16 + tt;
        unsigned long long acc[16];
#pragma unroll
        for (int i = 0; i < 16; i++) acc[i] = 0ull;
        const ulonglong2* hp = (const ulonglong2*)(g_h2 + ((size_t)t * Bsz + b) * HID);
#pragma unroll 2
        for (int kc = 0; kc < 128; kc++) {
            ulonglong2 h4 = __ldcg(hp + kc);
            int k = kc * 4;
#pragma unroll
            for (int i = 0; i < 16; i++) {
                const ulonglong2 w4 =
                    *(const ulonglong2*)(dsm + (vg + i * 4) * OW + k);
                fma2(acc[i], h4.x, w4.x);
                fma2(acc[i], h4.y, w4.y);
            }
        }
#pragma unroll
        for (int i = 0; i < 16; i++) {
            int v = vc * 64 + vg + i * 4;
            out[((size_t)b * Tlen + t) * 256 + v] = usum(acc[i]) + bo[i];
        }
    }
}

// ---------------- launch ----------------------------------------------------
extern "C" void kernel_launch(void* const* d_in, const int* in_sizes, int n_in,
                              void* d_out, int out_size) {
    (void)in_sizes; (void)n_in; (void)out_size;
    const float* ecc  = (const float*)d_in[0];
    const int*   cat  = (const int*)  d_in[1];
    const float* num  = (const float*)d_in[2];
    const int*   pay  = (const int*)  d_in[3];
    const float* e0   = (const float*)d_in[4];
    const float* e1   = (const float*)d_in[5];
    const float* e2   = (const float*)d_in[6];
    const float* be   = (const float*)d_in[7];
    const float* Wih0 = (const float*)d_in[8];
    const float* Whh0 = (const float*)d_in[9];
    const float* bih0 = (const float*)d_in[10];
    const float* bhh0 = (const float*)d_in[11];
    const float* Wih1 = (const float*)d_in[12];
    const float* Whh1 = (const float*)d_in[13];
    const float* bih1 = (const float*)d_in[14];
    const float* bhh1 = (const float*)d_in[15];
    const float* Wout = (const float*)d_in[16];
    const float* bout = (const float*)d_in[17];
    float* out = (float*)d_out;

    const int SM_L0  = (16 * WP + 16 * PP) * 4;   // 166,400 B
    const int SM_L1  = (2 * 16 * WP) * 4;         //  66,048 B
    const int SM_OUT = (64 * OW) * 4;             // 132,096 B
    cudaFuncSetAttribute(k_l0,  cudaFuncAttributeMaxDynamicSharedMemorySize, SM_L0);
    cudaFuncSetAttribute(k_l1,  cudaFuncAttributeMaxDynamicSharedMemorySize, SM_L1);
    cudaFuncSetAttribute(k_out, cudaFuncAttributeMaxDynamicSharedMemorySize, SM_OUT);

    k_prep <<<Bsz, 128>>>(ecc, cat, num, pay, e0, e1, e2);
    k_gctx <<<G4, 64>>>(Wih0, bih0, bhh0);
    k_table<<<G4, 256>>>(Wih0, be);
    k_l0   <<<GRIDR, 256, SM_L0>>>(Whh0);
    k_l1   <<<GRIDR, 256, SM_L1>>>(Whh1, Wih1, bih1, bhh1);
    dim3 go(4, 32);
    k_out  <<<go, 256, SM_OUT>>>(Wout, bout, out);
}

// round 8
// speedup vs baseline: 3.0322x; 1.1717x over previous
#include <cuda_runtime.h>
#include <math.h>
#include <stdint.h>

#define Bsz   64
#define Tlen  512
#define HID   512
#define G4    2048
#define CTX   792
#define IND   1048
#define BCL   8
#define VOC   260
#define PBL   (Tlen + BCL)   // 520
#define PJ    (BCL * VOC)    // 2080
#define WP    516            // padded row stride (mod 32 == 4 -> conflict-free)
#define GRIDR 128
#define UPB   4

// ---------------- device scratch ------------------------------------------
__device__ float g_ctx[Bsz * CTX];
__device__ int   g_pb[Bsz * PBL];
__device__ float g_gctx0[G4 * Bsz];                   // [g][b]
__device__ float g_PT[(size_t)PJ * G4];               // P transposed [j*260+v][g]
__device__ float g_gx[(size_t)Tlen * G4 * Bsz];       // gate preact [t][g][b] (268MB, reused l0/l1)
__device__ float g_h[2][Bsz * HID];                   // double-buffered h exchange
__device__ float g_h1[(size_t)Tlen * Bsz * HID];      // layer-0 outputs [t][b][k]
__device__ float g_h2[(size_t)Tlen * Bsz * HID];      // layer-1 outputs
__device__ unsigned g_flag[GRIDR];                    // barrier flags (monotonic)

// ---------------- helpers --------------------------------------------------
__device__ __forceinline__ void fma2(unsigned long long& acc,
                                     unsigned long long a, unsigned long long b) {
    asm("fma.rn.f32x2 %0, %1, %2, %0;" : "+l"(acc) : "l"(a), "l"(b));
}
__device__ __forceinline__ float usum(unsigned long long v) {
    float lo = __uint_as_float((unsigned)(v & 0xffffffffull));
    float hi = __uint_as_float((unsigned)(v >> 32));
    return lo + hi;
}
__device__ __forceinline__ float sigf(float x) {
    return __fdividef(1.f, 1.f + __expf(-x));
}
__device__ __forceinline__ float tanh_fast(float x) {
    return __fmaf_rn(2.f, sigf(2.f * x), -1.f);
}

__device__ __forceinline__ void bar_arrive(int bid, unsigned val) {
    asm volatile("st.release.gpu.global.u32 [%0], %1;"
                 :: "l"(g_flag + bid), "r"(val) : "memory");
}
__device__ __forceinline__ void bar_wait(unsigned target) {
    const unsigned* p = g_flag + ((threadIdx.x & 31) << 2);
    for (;;) {
        unsigned x, y, z, w;
        asm volatile("ld.relaxed.gpu.global.v4.u32 {%0,%1,%2,%3}, [%4];"
                     : "=r"(x), "=r"(y), "=r"(z), "=r"(w) : "l"(p));
        bool ok = (x >= target) && (y >= target) && (z >= target) && (w >= target);
        if (__all_sync(0xffffffffu, ok)) break;
    }
    asm volatile("fence.acq_rel.gpu;" ::: "memory");
}
__device__ __forceinline__ unsigned flag_base(int bid) {
    unsigned v;
    asm volatile("ld.relaxed.gpu.global.u32 %0, [%1];" : "=r"(v) : "l"(g_flag + bid));
    return v;
}

// ---------------- K0: context assembly + padded byte stream ----------------
__global__ void k_prep(const float* __restrict__ ecc, const int* __restrict__ cat,
                       const float* __restrict__ num, const int* __restrict__ pay,
                       const float* __restrict__ e0, const float* __restrict__ e1,
                       const float* __restrict__ e2) {
    int b = blockIdx.x;
    int c0 = cat[b * 3 + 0], c1 = cat[b * 3 + 1], c2 = cat[b * 3 + 2];
    for (int i = threadIdx.x; i < CTX; i += blockDim.x) {
        float v;
        if (i < 512)      v = ecc[b * 512 + i];
        else if (i < 562) v = e0[c0 * 50 + (i - 512)];
        else if (i < 626) v = e1[c1 * 64 + (i - 562)];
        else if (i < 776) v = e2[c2 * 150 + (i - 626)];
        else              v = num[b * 16 + (i - 776)];
        g_ctx[b * CTX + i] = v;
    }
    for (int p = threadIdx.x; p < PBL; p += blockDim.x) {
        int v = (p < BCL - 1) ? 256 : (p == BCL - 1 ? 257 : pay[b * Tlen + p - BCL]);
        g_pb[b * PBL + p] = v;
    }
}

// ---------------- K1: context gate projection (incl. both biases) ----------
__global__ void k_gctx(const float* __restrict__ Wih0, const float* __restrict__ bih0,
                       const float* __restrict__ bhh0) {
    int g = blockIdx.x;
    int b = threadIdx.x;
    const float* w = Wih0 + (size_t)g * IND;
    const float* c = g_ctx + b * CTX;
    float a0 = 0.f, a1 = 0.f, a2 = 0.f, a3 = 0.f;
    int k = 0;
    for (; k + 4 <= CTX; k += 4) {
        a0 += w[k] * c[k];     a1 += w[k+1] * c[k+1];
        a2 += w[k+2] * c[k+2]; a3 += w[k+3] * c[k+3];
    }
    for (; k < CTX; k++) a0 += w[k] * c[k];
    g_gctx0[g * Bsz + b] = a0 + a1 + a2 + a3 + bih0[g] + bhh0[g];
}

// ---------------- K2: transposed byte-projection table PT[j*260+v][g] ------
__global__ void k_table(const float* __restrict__ Wih0, const float* __restrict__ be) {
    __shared__ float ws[BCL * 32];
    __shared__ float es[VOC * 33];
    int g = blockIdx.x, tid = threadIdx.x;
    if (tid < 256) ws[tid] = Wih0[(size_t)g * IND + CTX + tid];
    for (int i = tid; i < VOC * 32; i += blockDim.x) {
        int v = i >> 5, k = i & 31;
        es[v * 33 + k] = be[i];
    }
    __syncthreads();
    for (int idx = tid; idx < PJ; idx += blockDim.x) {
        int j = idx / VOC, v = idx - j * VOC;
        const float* w = ws + j * 32;
        const float* e = es + v * 33;
        float acc = 0.f;
#pragma unroll
        for (int k = 0; k < 32; k++) acc += w[k] * e[k];
        g_PT[(size_t)idx * G4 + g] = acc;
    }
}

// ---------------- K3: layer-0 input preactivation gx0[t][g][b] -------------
__global__ void __launch_bounds__(256) k_gx0() {
    __shared__ int pbs[BCL * Bsz];
    __shared__ float os[128 * 65];
    int g0 = blockIdx.x * 128;
    int t  = blockIdx.y;
    int tid = threadIdx.x;
    for (int i = tid; i < BCL * Bsz; i += 256) {
        int j = i >> 6, b = i & 63;
        pbs[j * Bsz + b] = g_pb[b * PBL + t + j];
    }
    __syncthreads();
    int gl = tid & 127, bh = tid >> 7;
    for (int bi = 0; bi < 32; bi++) {
        int b = bh * 32 + bi;
        float acc = 0.f;
#pragma unroll
        for (int j = 0; j < BCL; j++) {
            int v = pbs[j * Bsz + b];
            acc += g_PT[(size_t)(j * VOC + v) * G4 + g0 + gl];
        }
        os[gl * 65 + b] = acc;
    }
    __syncthreads();
    float* out = g_gx + (size_t)t * G4 * Bsz;
    for (int i = tid; i < 128 * Bsz; i += 256) {
        int row = i >> 6, b = i & 63;
        out[(size_t)(g0 + row) * Bsz + b] = os[row * 65 + b]
                                          + g_gctx0[(g0 + row) * Bsz + b];
    }
}

// ---------------- K4: recurrence (shared by both layers) -------------------
// Block owns 4 hidden units. Per step: prefetch gx, barrier, stage h in smem,
// 16-row x 512 GEMM from smem, combine, publish h.
__global__ void __launch_bounds__(256) k_rec(const float* __restrict__ Whh,
                                             const float* __restrict__ gx,
                                             float* __restrict__ hist) {
    extern __shared__ float dsm[];
    float* Wsh = dsm;              // [16][WP]
    float* hs  = dsm + 16 * WP;    // [64][WP]
    __shared__ __align__(16) float ex[Bsz * 16];

    int tid = threadIdx.x, bid = blockIdx.x;
    int j0 = bid * UPB;
    unsigned base = flag_base(bid);

    for (int i = tid; i < 16 * HID; i += 256) {
        int lr = i >> 9, k = i & 511;
        int grow = ((lr & 3) << 9) + j0 + (lr >> 2);
        Wsh[lr * WP + k] = Whh[(size_t)grow * HID + k];
    }
    int b = tid >> 2, q = tid & 3;
    const float* wp_[UPB];
    size_t goff[UPB];
#pragma unroll
    for (int u = 0; u < UPB; u++) {
        wp_[u] = Wsh + (u * 4 + q) * WP;
        goff[u] = (size_t)((q << 9) + j0 + u) * Bsz + b;
    }
    float creg = 0.f;
    __syncthreads();

    for (int t = 0; t < Tlen; t++) {
        const float* gxt = g_gx == gx ? gx + (size_t)t * G4 * Bsz
                                      : gx + (size_t)t * G4 * Bsz; // keep simple
        float acc[UPB];
#pragma unroll
        for (int u = 0; u < UPB; u++) acc[u] = __ldcg(gxt + goff[u]);

        if (t > 0) {
            if (tid < 32) bar_wait(base + t);
            __syncthreads();
            // cooperative stage of h (coalesced LDG.128, padded STS)
            const float4* src = (const float4*)(g_h[t & 1]);
#pragma unroll
            for (int it = 0; it < 32; it++) {
                int i = tid + it * 256;
                float4 v = __ldcg(src + i);
                int bb = i >> 7, kv = i & 127;
                *(float4*)(hs + bb * WP + kv * 4) = v;
            }
            __syncthreads();
            const float* hb = hs + b * WP;
            unsigned long long a0[UPB] = {0,0,0,0}, a1[UPB] = {0,0,0,0};
#pragma unroll 8
            for (int k = 0; k < HID; k += 4) {
                ulonglong2 h4 = *(const ulonglong2*)(hb + k);
#pragma unroll
                for (int u = 0; u < UPB; u++) {
                    ulonglong2 w4 = *(const ulonglong2*)(wp_[u] + k);
                    fma2(a0[u], h4.x, w4.x);
                    fma2(a1[u], h4.y, w4.y);
                }
            }
#pragma unroll
            for (int u = 0; u < UPB; u++) acc[u] += usum(a0[u]) + usum(a1[u]);
        }
#pragma unroll
        for (int u = 0; u < UPB; u++) ex[b * 16 + u * 4 + q] = acc[u];
        __syncthreads();
        {
            float4 g = *(const float4*)(ex + b * 16 + q * 4);
            float c = sigf(g.y) * creg + sigf(g.x) * tanh_fast(g.z);
            float h = sigf(g.w) * tanh_fast(c);
            creg = c;
            int j = j0 + q;
            g_h[(t + 1) & 1][b * HID + j] = h;
            hist[((size_t)t * Bsz + b) * HID + j] = h;
        }
        __syncthreads();
        if (tid == 0) bar_arrive(bid, base + t + 1);
    }
}

// ---------------- K5: gx1 = bias + W_ih1 @ h1[t]  (tiled fp32 GEMM) --------
// grid (t=512, gtile=32), block 256. Tile [64 g][64 b], XOR-swizzled smem.
__global__ void __launch_bounds__(256) k_gx1(const float* __restrict__ Wih,
                                             const float* __restrict__ bi1,
                                             const float* __restrict__ bh1) {
    __shared__ float As[64 * 64];   // h1 tile  [b][k], xor-swizzled chunks
    __shared__ float Bs[64 * 64];   // W  tile  [g][k], xor-swizzled chunks
    int t = blockIdx.x, g0 = blockIdx.y * 64;
    int tid = threadIdx.x;
    int tg = tid >> 4, tb = tid & 15;           // 16 g-quads x 16 b-quads

    unsigned long long acc[4][4];
#pragma unroll
    for (int u = 0; u < 4; u++)
#pragma unroll
        for (int i = 0; i < 4; i++) acc[u][i] = 0ull;

    const float* A = g_h1 + (size_t)t * Bsz * HID;
    const float* B = Wih + (size_t)g0 * HID;

    for (int kt = 0; kt < 8; kt++) {
        int k0 = kt * 64;
        __syncthreads();
#pragma unroll
        for (int n = 0; n < 4; n++) {
            int i = tid + n * 256;              // 1024 float4 per tile
            int row = i >> 4, c = i & 15;
            int cs = c ^ ((row >> 2) & 7);
            float4 va = *(const float4*)(A + row * HID + k0 + c * 4);
            float4 vb = *(const float4*)(B + (size_t)row * HID + k0 + c * 4);
            *(float4*)(As + row * 64 + cs * 4) = va;
            *(float4*)(Bs + row * 64 + cs * 4) = vb;
        }
        __syncthreads();
#pragma unroll
        for (int c = 0; c < 16; c++) {
            ulonglong2 h4[4], w4[4];
            int ca = (c ^ (tb & 7)) << 2;
            int cb = (c ^ (tg & 7)) << 2;
#pragma unroll
            for (int i = 0; i < 4; i++)
                h4[i] = *(const ulonglong2*)(As + (tb * 4 + i) * 64 + ca);
#pragma unroll
            for (int u = 0; u < 4; u++)
                w4[u] = *(const ulonglong2*)(Bs + (tg * 4 + u) * 64 + cb);
#pragma unroll
            for (int u = 0; u < 4; u++)
#pragma unroll
                for (int i = 0; i < 4; i++) {
                    fma2(acc[u][i], w4[u].x, h4[i].x);
                    fma2(acc[u][i], w4[u].y, h4[i].y);
                }
        }
    }
    float* out = g_gx + (size_t)t * G4 * Bsz;
#pragma unroll
    for (int u = 0; u < 4; u++) {
        int g = g0 + tg * 4 + u;
        float bias = bi1[g] + bh1[g];
        float4 r;
        r.x = usum(acc[u][0]) + bias;
        r.y = usum(acc[u][1]) + bias;
        r.z = usum(acc[u][2]) + bias;
        r.w = usum(acc[u][3]) + bias;
        *(float4*)(out + (size_t)g * Bsz + tb * 4) = r;
    }
}

// ---------------- K6: output head ------------------------------------------
#define OW 516
__global__ void __launch_bounds__(256) k_out(const float* __restrict__ Wout,
                                             const float* __restrict__ bout,
                                             float* __restrict__ out) {
    extern __shared__ float dsm[];           // [64][OW]
    int vc = blockIdx.x;                     // 0..3
    int ts = blockIdx.y;                     // 0..31
    int tid = threadIdx.x;
    for (int i = tid; i < 64 * HID; i += 256) {
        int r = i >> 9, k = i & 511;
        dsm[r * OW + k] = Wout[(size_t)(vc * 64 + r) * HID + k];
    }
    __syncthreads();

    int b = tid >> 2, vg = tid & 3;
    float bo[16];
#pragma unroll
    for (int i = 0; i < 16; i++) bo[i] = bout[vc * 64 + vg + i * 4];

    for (int tt = 0; tt < 16; tt++) {
        int t = ts * 16 + tt;
        unsigned long long acc[16];
#pragma unroll
        for (int i = 0; i < 16; i++) acc[i] = 0ull;
        const ulonglong2* hp = (const ulonglong2*)(g_h2 + ((size_t)t * Bsz + b) * HID);
#pragma unroll 2
        for (int kc = 0; kc < 128; kc++) {
            ulonglong2 h4 = __ldcg(hp + kc);
            int k = kc * 4;
#pragma unroll
            for (int i = 0; i < 16; i++) {
                const ulonglong2 w4 =
                    *(const ulonglong2*)(dsm + (vg + i * 4) * OW + k);
                fma2(acc[i], h4.x, w4.x);
                fma2(acc[i], h4.y, w4.y);
            }
        }
#pragma unroll
        for (int i = 0; i < 16; i++) {
            int v = vc * 64 + vg + i * 4;
            out[((size_t)b * Tlen + t) * 256 + v] = usum(acc[i]) + bo[i];
        }
    }
}

// ---------------- launch ----------------------------------------------------
extern "C" void kernel_launch(void* const* d_in, const int* in_sizes, int n_in,
                              void* d_out, int out_size) {
    (void)in_sizes; (void)n_in; (void)out_size;
    const float* ecc  = (const float*)d_in[0];
    const int*   cat  = (const int*)  d_in[1];
    const float* num  = (const float*)d_in[2];
    const int*   pay  = (const int*)  d_in[3];
    const float* e0   = (const float*)d_in[4];
    const float* e1   = (const float*)d_in[5];
    const float* e2   = (const float*)d_in[6];
    const float* be   = (const float*)d_in[7];
    const float* Wih0 = (const float*)d_in[8];
    const float* Whh0 = (const float*)d_in[9];
    const float* bih0 = (const float*)d_in[10];
    const float* bhh0 = (const float*)d_in[11];
    const float* Wih1 = (const float*)d_in[12];
    const float* Whh1 = (const float*)d_in[13];
    const float* bih1 = (const float*)d_in[14];
    const float* bhh1 = (const float*)d_in[15];
    const float* Wout = (const float*)d_in[16];
    const float* bout = (const float*)d_in[17];
    float* out = (float*)d_out;

    float* gx;  cudaGetSymbolAddress((void**)&gx, g_gx);
    float* h1;  cudaGetSymbolAddress((void**)&h1, g_h1);
    float* h2;  cudaGetSymbolAddress((void**)&h2, g_h2);

    const int SM_REC = (16 * WP + 64 * WP) * 4;   // 165,120 B
    const int SM_OUT = (64 * OW) * 4;             // 132,096 B
    cudaFuncSetAttribute(k_rec, cudaFuncAttributeMaxDynamicSharedMemorySize, SM_REC);
    cudaFuncSetAttribute(k_out, cudaFuncAttributeMaxDynamicSharedMemorySize, SM_OUT);

    k_prep <<<Bsz, 128>>>(ecc, cat, num, pay, e0, e1, e2);
    k_gctx <<<G4, 64>>>(Wih0, bih0, bhh0);
    k_table<<<G4, 256>>>(Wih0, be);
    {
        dim3 gg(16, Tlen);
        k_gx0<<<gg, 256>>>();
    }
    k_rec  <<<GRIDR, 256, SM_REC>>>(Whh0, gx, h1);
    {
        dim3 gg(Tlen, 32);
        k_gx1<<<gg, 256>>>(Wih1, bih1, bhh1);
    }
    k_rec  <<<GRIDR, 256, SM_REC>>>(Whh1, gx, h2);
    {
        dim3 go(4, 32);
        k_out<<<go, 256, SM_OUT>>>(Wout, bout, out);
    }
}

// round 9
// speedup vs baseline: 3.2428x; 1.0695x over previous
#include <cuda_runtime.h>
#include <math.h>
#include <stdint.h>

#define Bsz   64
#define Tlen  512
#define HID   512
#define G4    2048
#define CTX   792
#define IND   1048
#define BCL   8
#define VOC   260
#define PBL   (Tlen + BCL)   // 520
#define PJ    (BCL * VOC)    // 2080
#define WP    516            // padded W row stride (mod 32 == 4 -> conflict-free)
#define HP    68             // padded h-chunk row stride (mod 32 == 4)
#define GRIDR 128
#define UPB   4
#define NCH   8              // h chunks per step (64 units each)

// ---------------- device scratch ------------------------------------------
__device__ float g_ctxT[CTX * Bsz];                   // transposed ctx [k][b]
__device__ int   g_pb[Bsz * PBL];
__device__ float g_gctx0[G4 * Bsz];                   // [g][b]
__device__ float g_PT[(size_t)PJ * G4];               // P transposed [j*260+v][g]
__device__ float g_gx[(size_t)Tlen * G4 * Bsz];       // gate preact [t][g][b]
__device__ float g_h[2][Bsz * HID];                   // depth-2 h ring
__device__ float g_h1[(size_t)Tlen * Bsz * HID];      // layer-0 outputs [t][b][k]
__device__ float g_h2[(size_t)Tlen * Bsz * HID];      // layer-1 outputs
__device__ unsigned g_ck0[Tlen * NCH];                // chunk counters layer 0
__device__ unsigned g_ck1[Tlen * NCH];                // chunk counters layer 1

// ---------------- helpers --------------------------------------------------
__device__ __forceinline__ void fma2(unsigned long long& acc,
                                     unsigned long long a, unsigned long long b) {
    asm("fma.rn.f32x2 %0, %1, %2, %0;" : "+l"(acc) : "l"(a), "l"(b));
}
__device__ __forceinline__ float usum(unsigned long long v) {
    float lo = __uint_as_float((unsigned)(v & 0xffffffffull));
    float hi = __uint_as_float((unsigned)(v >> 32));
    return lo + hi;
}
__device__ __forceinline__ float sigf(float x) {
    return __fdividef(1.f, 1.f + __expf(-x));
}
__device__ __forceinline__ float tanh_fast(float x) {
    return __fmaf_rn(2.f, sigf(2.f * x), -1.f);
}
__device__ __forceinline__ void cpasync16(uint32_t s, const void* g) {
    asm volatile("cp.async.cg.shared.global [%0], [%1], 16;" :: "r"(s), "l"(g));
}
__device__ __forceinline__ void waitcnt16(const unsigned* p) {
    unsigned v;
    do {
        asm volatile("ld.acquire.gpu.global.u32 %0, [%1];" : "=r"(v) : "l"(p));
    } while (v < 16u);
}
__device__ __forceinline__ void signal_chunk(unsigned* p) {
    asm volatile("red.release.gpu.global.add.u32 [%0], %1;" :: "l"(p), "r"(1u) : "memory");
}

// ---------------- K0: context assembly (transposed) + byte stream ----------
__global__ void k_prep(const float* __restrict__ ecc, const int* __restrict__ cat,
                       const float* __restrict__ num, const int* __restrict__ pay,
                       const float* __restrict__ e0, const float* __restrict__ e1,
                       const float* __restrict__ e2) {
    int b = blockIdx.x;
    int c0 = cat[b * 3 + 0], c1 = cat[b * 3 + 1], c2 = cat[b * 3 + 2];
    for (int i = threadIdx.x; i < CTX; i += blockDim.x) {
        float v;
        if (i < 512)      v = ecc[b * 512 + i];
        else if (i < 562) v = e0[c0 * 50 + (i - 512)];
        else if (i < 626) v = e1[c1 * 64 + (i - 562)];
        else if (i < 776) v = e2[c2 * 150 + (i - 626)];
        else              v = num[b * 16 + (i - 776)];
        g_ctxT[i * Bsz + b] = v;
    }
    for (int p = threadIdx.x; p < PBL; p += blockDim.x) {
        int v = (p < BCL - 1) ? 256 : (p == BCL - 1 ? 257 : pay[b * Tlen + p - BCL]);
        g_pb[b * PBL + p] = v;
    }
}

// ---------------- K1: context gate projection (coalesced) ------------------
__global__ void k_gctx(const float* __restrict__ Wih0, const float* __restrict__ bih0,
                       const float* __restrict__ bhh0) {
    int g = blockIdx.x;
    int b = threadIdx.x;
    const float* w = Wih0 + (size_t)g * IND;
    float a0 = 0.f, a1 = 0.f, a2 = 0.f, a3 = 0.f;
    int k = 0;
    for (; k + 4 <= CTX; k += 4) {
        a0 += w[k]   * g_ctxT[k * Bsz + b];
        a1 += w[k+1] * g_ctxT[(k+1) * Bsz + b];
        a2 += w[k+2] * g_ctxT[(k+2) * Bsz + b];
        a3 += w[k+3] * g_ctxT[(k+3) * Bsz + b];
    }
    for (; k < CTX; k++) a0 += w[k] * g_ctxT[k * Bsz + b];
    g_gctx0[g * Bsz + b] = a0 + a1 + a2 + a3 + bih0[g] + bhh0[g];
}

// ---------------- K2: transposed byte-projection table PT[j*260+v][g] ------
__global__ void k_table(const float* __restrict__ Wih0, const float* __restrict__ be) {
    __shared__ float ws[BCL * 32];
    __shared__ float es[VOC * 33];
    int g = blockIdx.x, tid = threadIdx.x;
    if (tid < 256) ws[tid] = Wih0[(size_t)g * IND + CTX + tid];
    for (int i = tid; i < VOC * 32; i += blockDim.x) {
        int v = i >> 5, k = i & 31;
        es[v * 33 + k] = be[i];
    }
    __syncthreads();
    for (int idx = tid; idx < PJ; idx += blockDim.x) {
        int j = idx / VOC, v = idx - j * VOC;
        const float* w = ws + j * 32;
        const float* e = es + v * 33;
        float acc = 0.f;
#pragma unroll
        for (int k = 0; k < 32; k++) acc += w[k] * e[k];
        g_PT[(size_t)idx * G4 + g] = acc;
    }
}

// ---------------- K3: layer-0 input preactivation gx0[t][g][b] -------------
__global__ void __launch_bounds__(256) k_gx0() {
    __shared__ int pbs[BCL * Bsz];
    __shared__ float os[128 * 65];
    int g0 = blockIdx.x * 128;
    int t  = blockIdx.y;
    int tid = threadIdx.x;
    for (int i = tid; i < BCL * Bsz; i += 256) {
        int j = i >> 6, b = i & 63;
        pbs[j * Bsz + b] = g_pb[b * PBL + t + j];
    }
    __syncthreads();
    int gl = tid & 127, bh = tid >> 7;
    for (int bi = 0; bi < 32; bi++) {
        int b = bh * 32 + bi;
        float acc = 0.f;
#pragma unroll
        for (int j = 0; j < BCL; j++) {
            int v = pbs[j * Bsz + b];
            acc += g_PT[(size_t)(j * VOC + v) * G4 + g0 + gl];
        }
        os[gl * 65 + b] = acc;
    }
    __syncthreads();
    float* out = g_gx + (size_t)t * G4 * Bsz;
    for (int i = tid; i < 128 * Bsz; i += 256) {
        int row = i >> 6, b = i & 63;
        out[(size_t)(g0 + row) * Bsz + b] = os[row * 65 + b]
                                          + g_gctx0[(g0 + row) * Bsz + b];
    }
}

// ---------------- K4: recurrence — chunked dataflow, no global barrier -----
// Block owns 4 hidden units (chunk = bid>>4). h consumed in 8 chunks of 64
// units; per-chunk release counters; cp.async double-buffered staging.
__global__ void __launch_bounds__(256) k_rec(const float* __restrict__ Whh,
                                             const float* __restrict__ gx,
                                             float* __restrict__ hist,
                                             unsigned* __restrict__ ck) {
    extern __shared__ float dsm[];
    float* Wsh = dsm;                        // [16][WP]
    float* hbuf[2] = { dsm + 16 * WP, dsm + 16 * WP + 64 * HP };
    __shared__ __align__(16) float ex[Bsz * 16];

    int tid = threadIdx.x, bid = blockIdx.x;
    int j0 = bid * UPB;
    int mych = bid >> 4;

    for (int i = tid; i < 16 * HID; i += 256) {
        int lr = i >> 9, k = i & 511;
        int grow = ((lr & 3) << 9) + j0 + (lr >> 2);
        Wsh[lr * WP + k] = Whh[(size_t)grow * HID + k];
    }
    int b = tid >> 2, q = tid & 3;
    const float* wp_[UPB];
    size_t goff[UPB];
#pragma unroll
    for (int u = 0; u < UPB; u++) {
        wp_[u] = Wsh + (u * 4 + q) * WP;
        goff[u] = (size_t)((q << 9) + j0 + u) * Bsz + b;
    }
    // per-thread staging slots: 4 float4 per chunk
    int sb[4], sk[4];
    uint32_t sdst[2][4];
#pragma unroll
    for (int n = 0; n < 4; n++) {
        int idx = tid + n * 256;
        sb[n] = idx >> 4; sk[n] = idx & 15;
        sdst[0][n] = (uint32_t)__cvta_generic_to_shared(hbuf[0] + sb[n] * HP + sk[n] * 4);
        sdst[1][n] = (uint32_t)__cvta_generic_to_shared(hbuf[1] + sb[n] * HP + sk[n] * 4);
    }
    float creg = 0.f;
    __syncthreads();

    for (int t = 0; t < Tlen; t++) {
        float acc[UPB];
        const float* gxt = gx + (size_t)t * G4 * Bsz;
#pragma unroll
        for (int u = 0; u < UPB; u++) acc[u] = __ldcg(gxt + goff[u]);

        if (t > 0) {
            const float4* src = (const float4*)(g_h[t & 1]);
            const unsigned* ckt = ck + (size_t)(t - 1) * NCH;
            // prime chunk 0
            if (tid == 0) waitcnt16(ckt);
            __syncthreads();
#pragma unroll
            for (int n = 0; n < 4; n++)
                cpasync16(sdst[0][n], src + sb[n] * 128 + sk[n]);
            asm volatile("cp.async.commit_group;");

            unsigned long long a0[UPB] = {0,0,0,0}, a1[UPB] = {0,0,0,0};
            for (int c = 0; c < NCH; c++) {
                if (c < NCH - 1) {
                    if (tid == 0) waitcnt16(ckt + c + 1);
                    __syncthreads();   // also protects buf[(c+1)&1] from prior GEMM readers
                    int nb = (c + 1) & 1;
#pragma unroll
                    for (int n = 0; n < 4; n++)
                        cpasync16(sdst[nb][n], src + sb[n] * 128 + (c + 1) * 16 + sk[n]);
                    asm volatile("cp.async.commit_group;");
                    asm volatile("cp.async.wait_group 1;");
                } else {
                    asm volatile("cp.async.wait_group 0;");
                }
                __syncthreads();       // all threads' cp data visible
                const float* hb = hbuf[c & 1] + b * HP;
#pragma unroll
                for (int kk = 0; kk < 64; kk += 4) {
                    ulonglong2 h4 = *(const ulonglong2*)(hb + kk);
#pragma unroll
                    for (int u = 0; u < UPB; u++) {
                        ulonglong2 w4 = *(const ulonglong2*)(wp_[u] + c * 64 + kk);
                        fma2(a0[u], h4.x, w4.x);
                        fma2(a1[u], h4.y, w4.y);
                    }
                }
            }
#pragma unroll
            for (int u = 0; u < UPB; u++) acc[u] += usum(a0[u]) + usum(a1[u]);
        }
#pragma unroll
        for (int u = 0; u < UPB; u++) ex[b * 16 + u * 4 + q] = acc[u];
        __syncthreads();
        {
            float4 g = *(const float4*)(ex + b * 16 + q * 4);
            float c = sigf(g.y) * creg + sigf(g.x) * tanh_fast(g.z);
            float h = sigf(g.w) * tanh_fast(c);
            creg = c;
            int j = j0 + q;
            g_h[(t + 1) & 1][b * HID + j] = h;
            hist[((size_t)t * Bsz + b) * HID + j] = h;
        }
        __syncthreads();
        if (tid == 0) signal_chunk(ck + (size_t)t * NCH + mych);
    }
}

// ---------------- K5: gx1 = bias + W_ih1 @ h1[t]  (tiled fp32 GEMM) --------
__global__ void __launch_bounds__(256) k_gx1(const float* __restrict__ Wih,
                                             const float* __restrict__ bi1,
                                             const float* __restrict__ bh1) {
    __shared__ float As[64 * 64];
    __shared__ float Bs[64 * 64];
    int t = blockIdx.x, g0 = blockIdx.y * 64;
    int tid = threadIdx.x;
    int tg = tid >> 4, tb = tid & 15;

    unsigned long long acc[4][4];
#pragma unroll
    for (int u = 0; u < 4; u++)
#pragma unroll
        for (int i = 0; i < 4; i++) acc[u][i] = 0ull;

    const float* A = g_h1 + (size_t)t * Bsz * HID;
    const float* B = Wih + (size_t)g0 * HID;

    for (int kt = 0; kt < 8; kt++) {
        int k0 = kt * 64;
        __syncthreads();
#pragma unroll
        for (int n = 0; n < 4; n++) {
            int i = tid + n * 256;
            int row = i >> 4, c = i & 15;
            int cs = c ^ ((row >> 2) & 7);
            float4 va = *(const float4*)(A + row * HID + k0 + c * 4);
            float4 vb = *(const float4*)(B + (size_t)row * HID + k0 + c * 4);
            *(float4*)(As + row * 64 + cs * 4) = va;
            *(float4*)(Bs + row * 64 + cs * 4) = vb;
        }
        __syncthreads();
#pragma unroll
        for (int c = 0; c < 16; c++) {
            ulonglong2 h4[4], w4[4];
            int ca = (c ^ (tb & 7)) << 2;
            int cb = (c ^ (tg & 7)) << 2;
#pragma unroll
            for (int i = 0; i < 4; i++)
                h4[i] = *(const ulonglong2*)(As + (tb * 4 + i) * 64 + ca);
#pragma unroll
            for (int u = 0; u < 4; u++)
                w4[u] = *(const ulonglong2*)(Bs + (tg * 4 + u) * 64 + cb);
#pragma unroll
            for (int u = 0; u < 4; u++)
#pragma unroll
                for (int i = 0; i < 4; i++) {
                    fma2(acc[u][i], w4[u].x, h4[i].x);
                    fma2(acc[u][i], w4[u].y, h4[i].y);
                }
        }
    }
    float* out = g_gx + (size_t)t * G4 * Bsz;
#pragma unroll
    for (int u = 0; u < 4; u++) {
        int g = g0 + tg * 4 + u;
        float bias = bi1[g] + bh1[g];
        float4 r;
        r.x = usum(acc[u][0]) + bias;
        r.y = usum(acc[u][1]) + bias;
        r.z = usum(acc[u][2]) + bias;
        r.w = usum(acc[u][3]) + bias;
        *(float4*)(out + (size_t)g * Bsz + tb * 4) = r;
    }
}

// ---------------- K6: output head ------------------------------------------
#define OW 516
__global__ void __launch_bounds__(256) k_out(const float* __restrict__ Wout,
                                             const float* __restrict__ bout,
                                             float* __restrict__ out) {
    extern __shared__ float dsm[];           // [64][OW]
    int vc = blockIdx.x;                     // 0..3
    int ts = blockIdx.y;                     // 0..31
    int tid = threadIdx.x;
    for (int i = tid; i < 64 * HID; i += 256) {
        int r = i >> 9, k = i & 511;
        dsm[r * OW + k] = Wout[(size_t)(vc * 64 + r) * HID + k];
    }
    __syncthreads();

    int b = tid >> 2, vg = tid & 3;
    float bo[16];
#pragma unroll
    for (int i = 0; i < 16; i++) bo[i] = bout[vc * 64 + vg + i * 4];

    for (int tt = 0; tt < 16; tt++) {
        int t = ts * 16 + tt;
        unsigned long long acc[16];
#pragma unroll
        for (int i = 0; i < 16; i++) acc[i] = 0ull;
        const ulonglong2* hp = (const ulonglong2*)(g_h2 + ((size_t)t * Bsz + b) * HID);
#pragma unroll 2
        for (int kc = 0; kc < 128; kc++) {
            ulonglong2 h4 = __ldcg(hp + kc);
            int k = kc * 4;
#pragma unroll
            for (int i = 0; i < 16; i++) {
                const ulonglong2 w4 =
                    *(const ulonglong2*)(dsm + (vg + i * 4) * OW + k);
                fma2(acc[i], h4.x, w4.x);
                fma2(acc[i], h4.y, w4.y);
            }
        }
#pragma unroll
        for (int i = 0; i < 16; i++) {
            int v = vc * 64 + vg + i * 4;
            out[((size_t)b * Tlen + t) * 256 + v] = usum(acc[i]) + bo[i];
        }
    }
}

// ---------------- launch ----------------------------------------------------
extern "C" void kernel_launch(void* const* d_in, const int* in_sizes, int n_in,
                              void* d_out, int out_size) {
    (void)in_sizes; (void)n_in; (void)out_size;
    const float* ecc  = (const float*)d_in[0];
    const int*   cat  = (const int*)  d_in[1];
    const float* num  = (const float*)d_in[2];
    const int*   pay  = (const int*)  d_in[3];
    const float* e0   = (const float*)d_in[4];
    const float* e1   = (const float*)d_in[5];
    const float* e2   = (const float*)d_in[6];
    const float* be   = (const float*)d_in[7];
    const float* Wih0 = (const float*)d_in[8];
    const float* Whh0 = (const float*)d_in[9];
    const float* bih0 = (const float*)d_in[10];
    const float* bhh0 = (const float*)d_in[11];
    const float* Wih1 = (const float*)d_in[12];
    const float* Whh1 = (const float*)d_in[13];
    const float* bih1 = (const float*)d_in[14];
    const float* bhh1 = (const float*)d_in[15];
    const float* Wout = (const float*)d_in[16];
    const float* bout = (const float*)d_in[17];
    float* out = (float*)d_out;

    float* gx;     cudaGetSymbolAddress((void**)&gx,  g_gx);
    float* h1;     cudaGetSymbolAddress((void**)&h1,  g_h1);
    float* h2;     cudaGetSymbolAddress((void**)&h2,  g_h2);
    unsigned* ck0; cudaGetSymbolAddress((void**)&ck0, g_ck0);
    unsigned* ck1; cudaGetSymbolAddress((void**)&ck1, g_ck1);

    const int SM_REC = (16 * WP + 2 * 64 * HP) * 4;   // 67,840 B
    const int SM_OUT = (64 * OW) * 4;                 // 132,096 B
    cudaFuncSetAttribute(k_rec, cudaFuncAttributeMaxDynamicSharedMemorySize, SM_REC);
    cudaFuncSetAttribute(k_out, cudaFuncAttributeMaxDynamicSharedMemorySize, SM_OUT);

    cudaMemsetAsync(ck0, 0, Tlen * NCH * sizeof(unsigned));
    cudaMemsetAsync(ck1, 0, Tlen * NCH * sizeof(unsigned));

    k_prep <<<Bsz, 128>>>(ecc, cat, num, pay, e0, e1, e2);
    k_gctx <<<G4, 64>>>(Wih0, bih0, bhh0);
    k_table<<<G4, 256>>>(Wih0, be);
    {
        dim3 gg(16, Tlen);
        k_gx0<<<gg, 256>>>();
    }
    k_rec  <<<GRIDR, 256, SM_REC>>>(Whh0, gx, h1, ck0);
    {
        dim3 gg(Tlen, 32);
        k_gx1<<<gg, 256>>>(Wih1, bih1, bhh1);
    }
    k_rec  <<<GRIDR, 256, SM_REC>>>(Whh1, gx, h2, ck1);
    {
        dim3 go(4, 32);
        k_out<<<go, 256, SM_OUT>>>(Wout, bout, out);
    }
}